// round 1
// baseline (speedup 1.0000x reference)
#include <cuda_runtime.h>
#include <math.h>

#define DD 48
#define VV (48*48*48)          // 110592 voxels
#define KK 9
#define EPSF 1e-5f

// ---------------- scratch (static device globals; no allocation) ----------------
__device__ float  g_xl [(size_t)VV * 16];   // x transposed to [z][y][x][ci]   (7 MB)
__device__ float  g_off[(size_t)18 * VV];   // offset conv out (18 ch)         (8 MB)
__device__ float  g_pre[(size_t)32 * VV];   // pre-groupnorm snake conv out    (14 MB)
__device__ double g_part[8 * 16 * 2];       // per-(group,block) partial sums
__device__ float  g_mean[8], g_rstd[8];

// ---------------- K0: transpose x -> channel-last ----------------
__global__ void transpose_k(const float* __restrict__ x) {
    int vox = blockIdx.x * 128 + threadIdx.x;
    if (vox >= VV) return;
    float t[16];
#pragma unroll
    for (int ci = 0; ci < 16; ci++) t[ci] = x[(size_t)ci * VV + vox];
    float4* dst = (float4*)(g_xl + (size_t)vox * 16);
    dst[0] = make_float4(t[0],  t[1],  t[2],  t[3]);
    dst[1] = make_float4(t[4],  t[5],  t[6],  t[7]);
    dst[2] = make_float4(t[8],  t[9],  t[10], t[11]);
    dst[3] = make_float4(t[12], t[13], t[14], t[15]);
}

// ---------------- K1: offset conv (only 18 of 54 channels) + BN(eval) + tanh ----
// grid (48,48) = (w,d); block (48,6): tx=h, ty -> 3 output channels each.
// Two ci-phases of 8 channels keep static smem < 48 KB.
__global__ void offset_conv_k(const float* __restrict__ x,
                              const float* __restrict__ ow,
                              const float* __restrict__ ob,
                              const float* __restrict__ bn_g,
                              const float* __restrict__ bn_b,
                              const float* __restrict__ bn_m,
                              const float* __restrict__ bn_v) {
    __shared__ float sx[8][3][3][50];   // 3600 floats
    __shared__ float sw[3888];          // [co(18)][ci(8)][27]

    int w  = blockIdx.x, d = blockIdx.y;
    int tid = threadIdx.y * 48 + threadIdx.x;   // 288 threads
    int h  = threadIdx.x;
    int co0 = threadIdx.y * 3;

    float a0 = 0.f, a1 = 0.f, a2 = 0.f;

    for (int p = 0; p < 2; p++) {
        __syncthreads();
        for (int e = tid; e < 3600; e += 288) {
            int ci = e / 450, r = e % 450;
            int dz = r / 150; r %= 150;
            int dy = r / 50, hh = r % 50;
            int z = d + dz - 1, y = w + dy - 1, xx = hh - 1;
            float v = 0.f;
            if ((unsigned)z < 48u && (unsigned)y < 48u && (unsigned)xx < 48u)
                v = x[((size_t)(ci + 8 * p) * VV) + ((size_t)z * 48 + y) * 48 + xx];
            sx[ci][dz][dy][hh] = v;
        }
        for (int e = tid; e < 3888; e += 288) {
            int co = e / 216, r = e % 216;
            int ci = r / 27, t = r % 27;
            sw[e] = ow[(size_t)(co * 16 + ci + 8 * p) * 27 + t];
        }
        __syncthreads();
#pragma unroll
        for (int ci = 0; ci < 8; ci++) {
#pragma unroll
            for (int dz = 0; dz < 3; dz++) {
#pragma unroll
                for (int dy = 0; dy < 3; dy++) {
                    float v0 = sx[ci][dz][dy][h];
                    float v1 = sx[ci][dz][dy][h + 1];
                    float v2 = sx[ci][dz][dy][h + 2];
                    int b0 = (co0 * 8 + ci) * 27 + dz * 9 + dy * 3;
                    a0 += v0 * sw[b0]       + v1 * sw[b0 + 1]       + v2 * sw[b0 + 2];
                    a1 += v0 * sw[b0 + 216] + v1 * sw[b0 + 217]     + v2 * sw[b0 + 218];
                    a2 += v0 * sw[b0 + 432] + v1 * sw[b0 + 433]     + v2 * sw[b0 + 434];
                }
            }
        }
    }

    int vo = ((size_t)d * 48 + w) * 48 + h;
    float accs[3] = {a0, a1, a2};
#pragma unroll
    for (int j = 0; j < 3; j++) {
        int c = co0 + j;
        float al  = bn_g[c] * rsqrtf(bn_v[c] + EPSF);
        float val = tanhf((accs[j] + ob[c] - bn_m[c]) * al + bn_b[c]);
        g_off[(size_t)c * VV + vo] = val;
    }
}

// ---------------- K2: fused snake-cumsum + trilinear gather + (1,1,9) conv ------
__global__ __launch_bounds__(128) void dsc_k(const float* __restrict__ dwt,
                                             const float* __restrict__ db) {
    __shared__ float s_dw[16 * 9 * 32];     // [ci][k][co]
    __shared__ float s_cz[9][128];
    __shared__ float s_cy[9][128];

    int tid = threadIdx.x;
    for (int e = tid; e < 4608; e += 128) {
        int co = e / 144, r = e % 144;
        int ci = r / 9, k = r % 9;
        s_dw[(ci * 9 + k) * 32 + co] = dwt[e];
    }

    int vox = blockIdx.x * 128 + tid;       // 864 blocks * 128 = VV exactly
    int h = vox % 48;
    int t2 = vox / 48;
    int wq = t2 % 48;
    int dq = t2 / 48;

    {   // cumulative snake offsets, center forced to zero
        float o[9];
#pragma unroll
        for (int k = 0; k < 9; k++) o[k] = g_off[(size_t)k * VV + vox];
        float c3 = o[3], c2 = o[2] + c3, c1 = o[1] + c2, c0 = o[0] + c1;
        float c5 = o[5], c6 = o[6] + c5, c7 = o[7] + c6, c8 = o[8] + c7;
        s_cz[0][tid] = c0; s_cz[1][tid] = c1; s_cz[2][tid] = c2; s_cz[3][tid] = c3;
        s_cz[4][tid] = 0.f;
        s_cz[5][tid] = c5; s_cz[6][tid] = c6; s_cz[7][tid] = c7; s_cz[8][tid] = c8;
#pragma unroll
        for (int k = 0; k < 9; k++) o[k] = g_off[(size_t)(9 + k) * VV + vox];
        c3 = o[3]; c2 = o[2] + c3; c1 = o[1] + c2; c0 = o[0] + c1;
        c5 = o[5]; c6 = o[6] + c5; c7 = o[7] + c6; c8 = o[8] + c7;
        s_cy[0][tid] = c0; s_cy[1][tid] = c1; s_cy[2][tid] = c2; s_cy[3][tid] = c3;
        s_cy[4][tid] = 0.f;
        s_cy[5][tid] = c5; s_cy[6][tid] = c6; s_cy[7][tid] = c7; s_cy[8][tid] = c8;
    }
    __syncthreads();

    float acc[32];
#pragma unroll
    for (int co = 0; co < 32; co++) acc[co] = db[co];

    for (int k = 0; k < 9; k++) {
        float z  = (float)dq + s_cz[k][tid];
        float y  = (float)wq + s_cy[k][tid];
        float xf = (float)(h + k - 4);
        z  = fminf(fmaxf(z,  0.f), 47.f);
        y  = fminf(fmaxf(y,  0.f), 47.f);
        xf = fminf(fmaxf(xf, 0.f), 47.f);
        int z0 = (int)floorf(z);  int z1 = min(z0 + 1, 47);
        int y0 = (int)floorf(y);  int y1 = min(y0 + 1, 47);
        int x0 = (int)floorf(xf); int x1 = min(x0 + 1, 47);
        float wz1 = z  - (float)z0, wz0 = (float)z1 - z;
        float wy1 = y  - (float)y0, wy0 = (float)y1 - y;
        float wx1 = xf - (float)x0, wx0 = (float)x1 - xf;

        float s[16];
#pragma unroll
        for (int q = 0; q < 16; q++) s[q] = 0.f;

        int r00 = (z0 * 48 + y0) * 48;
        int r01 = (z0 * 48 + y1) * 48;
        int r10 = (z1 * 48 + y0) * 48;
        int r11 = (z1 * 48 + y1) * 48;

#define CORNER(ri, xi, wgt) {                                                   \
        const float4* p = (const float4*)(g_xl + (size_t)((ri) + (xi)) * 16);   \
        float wv = (wgt);                                                       \
        float4 A = p[0], B = p[1], C = p[2], E = p[3];                          \
        s[0]  += wv * A.x; s[1]  += wv * A.y; s[2]  += wv * A.z; s[3]  += wv * A.w; \
        s[4]  += wv * B.x; s[5]  += wv * B.y; s[6]  += wv * B.z; s[7]  += wv * B.w; \
        s[8]  += wv * C.x; s[9]  += wv * C.y; s[10] += wv * C.z; s[11] += wv * C.w; \
        s[12] += wv * E.x; s[13] += wv * E.y; s[14] += wv * E.z; s[15] += wv * E.w; }

        CORNER(r00, x0, wz0 * wy0 * wx0);
        CORNER(r00, x1, wz0 * wy0 * wx1);
        CORNER(r01, x0, wz0 * wy1 * wx0);
        CORNER(r01, x1, wz0 * wy1 * wx1);
        CORNER(r10, x0, wz1 * wy0 * wx0);
        CORNER(r10, x1, wz1 * wy0 * wx1);
        CORNER(r11, x0, wz1 * wy1 * wx0);
        CORNER(r11, x1, wz1 * wy1 * wx1);
#undef CORNER

#pragma unroll
        for (int ci = 0; ci < 16; ci++) {
            float sv = s[ci];
            const float* wp = &s_dw[(ci * 9 + k) * 32];
#pragma unroll
            for (int co = 0; co < 32; co++) acc[co] += sv * wp[co];
        }
    }

#pragma unroll
    for (int co = 0; co < 32; co++) g_pre[(size_t)co * VV + vox] = acc[co];
}

// ---------------- K3: per-(group, block) deterministic partial reduction --------
__global__ void gsum_k() {
    int g = blockIdx.y;                    // 0..7
    const float* p = g_pre + (size_t)g * 4 * VV;
    const int n = 4 * VV;                  // 442368
    double s = 0.0, q = 0.0;
    for (int i = blockIdx.x * 256 + threadIdx.x; i < n; i += 16 * 256) {
        float v = p[i];
        s += (double)v;
        q += (double)v * (double)v;
    }
    __shared__ double sh[256];
    sh[threadIdx.x] = s; __syncthreads();
    for (int st = 128; st > 0; st >>= 1) {
        if (threadIdx.x < st) sh[threadIdx.x] += sh[threadIdx.x + st];
        __syncthreads();
    }
    if (threadIdx.x == 0) g_part[(g * 16 + blockIdx.x) * 2] = sh[0];
    __syncthreads();
    sh[threadIdx.x] = q; __syncthreads();
    for (int st = 128; st > 0; st >>= 1) {
        if (threadIdx.x < st) sh[threadIdx.x] += sh[threadIdx.x + st];
        __syncthreads();
    }
    if (threadIdx.x == 0) g_part[(g * 16 + blockIdx.x) * 2 + 1] = sh[0];
}

// ---------------- K4: combine partials in fixed order -> mean / rstd ------------
__global__ void stats_k() {
    int g = threadIdx.x;
    if (g < 8) {
        double s = 0.0, q = 0.0;
        for (int b = 0; b < 16; b++) {
            s += g_part[(g * 16 + b) * 2];
            q += g_part[(g * 16 + b) * 2 + 1];
        }
        double n   = 4.0 * (double)VV;
        double mu  = s / n;
        double var = q / n - mu * mu;
        g_mean[g] = (float)mu;
        g_rstd[g] = (float)(1.0 / sqrt(var + 1e-5));
    }
}

// ---------------- K5: groupnorm apply + relu -----------------------------------
__global__ void finalize_k(const float* __restrict__ gn_g,
                           const float* __restrict__ gn_b,
                           float* __restrict__ out) {
    int i = blockIdx.x * 256 + threadIdx.x;
    if (i >= 32 * VV) return;
    int c = i / VV;
    int g = c >> 2;
    float v = g_pre[i];
    float r = (v - g_mean[g]) * g_rstd[g] * gn_g[c] + gn_b[c];
    out[i] = fmaxf(r, 0.f);
}

// ---------------- launch --------------------------------------------------------
extern "C" void kernel_launch(void* const* d_in, const int* in_sizes, int n_in,
                              void* d_out, int out_size) {
    const float* x    = (const float*)d_in[0];
    const float* ow   = (const float*)d_in[1];
    const float* ob   = (const float*)d_in[2];
    const float* bn_g = (const float*)d_in[3];
    const float* bn_b = (const float*)d_in[4];
    const float* bn_m = (const float*)d_in[5];
    const float* bn_v = (const float*)d_in[6];
    const float* dw   = (const float*)d_in[7];
    const float* db   = (const float*)d_in[8];
    const float* gn_g = (const float*)d_in[9];
    const float* gn_b = (const float*)d_in[10];
    float* out = (float*)d_out;

    transpose_k<<<VV / 128, 128>>>(x);
    offset_conv_k<<<dim3(48, 48), dim3(48, 6)>>>(x, ow, ob, bn_g, bn_b, bn_m, bn_v);
    dsc_k<<<VV / 128, 128>>>(dw, db);
    gsum_k<<<dim3(16, 8), 256>>>();
    stats_k<<<1, 32>>>();
    finalize_k<<<(32 * VV + 255) / 256, 256>>>(gn_g, gn_b, out);
}